// round 7
// baseline (speedup 1.0000x reference)
#include <cuda_runtime.h>
#include <cuda_fp16.h>
#include <cstdint>

#define N_CAP 100000
#define E_CAP 1600000

// ---------------- scratch (__device__ globals) ----------------
__device__ float  g_dinv[2][N_CAP];
__device__ int    g_deg[2][N_CAP];
__device__ int    g_incl[2][N_CAP];
__device__ int    g_rowptr[2][N_CAP + 1];
__device__ int    g_bsum[2][128];
__device__ int    g_rank[2][E_CAP];             // per-edge rank within its dst row
__device__ int    g_esrc[2][E_CAP];             // dst-sorted src ids
__device__ __half g_A[2][(size_t)N_CAP * 64];   // h' = dinv * (X @ W), fp16
__device__ float  g_B[2][(size_t)N_CAP * 64];   // fp32 staging (h, then Z1)

static __device__ __forceinline__ int clampi(int v, int lo, int hi) {
    return v < lo ? lo : (v > hi ? hi : v);
}

// ---------------- merged: hist (rank-claiming) + layer-1 GEMM (fp32 -> g_B) ------
// blocks [0, nb_e): hist; blocks [nb_e, nb_e+nb_g): gemm h = X @ W1 (unscaled fp32)

__global__ void histgemm_kernel(const int* __restrict__ e0, const int* __restrict__ e1,
                                const float* __restrict__ X0, const float* __restrict__ X1,
                                const float* __restrict__ W, int E, int n, int nb_e) {
    __shared__ float Ws[64][64];
    __shared__ float Xs[64][65];
    int g = blockIdx.y;
    int tid = threadIdx.x;

    if ((int)blockIdx.x < nb_e) {
        const int* base = (g == 0 ? e0 : e1);
        int e = blockIdx.x * 256 + tid;
        if (e < E) {
            int d = clampi(base[E + e], 0, n - 1);
            g_rank[g][e] = atomicAdd(&g_deg[g][d], 1);  // rank within dst row
        }
        return;
    }

    const float* X = (g == 0 ? X0 : X1);
    float* Y = g_B[g];
    for (int i = tid; i < 64 * 16; i += 256)
        ((float4*)Ws)[i] = ((const float4*)W)[i];
    int row0 = (blockIdx.x - nb_e) * 64;
    for (int i = tid; i < 64 * 16; i += 256) {
        int r = i >> 4, c = (i & 15) * 4;
        float4 v = make_float4(0.f, 0.f, 0.f, 0.f);
        if (row0 + r < n) v = *(const float4*)&X[(size_t)(row0 + r) * 64 + c];
        Xs[r][c] = v.x; Xs[r][c + 1] = v.y; Xs[r][c + 2] = v.z; Xs[r][c + 3] = v.w;
    }
    __syncthreads();
    int tr = (tid >> 4) * 4;
    int tc = tid & 15;
    float acc[4][4] = {};
#pragma unroll
    for (int k = 0; k < 64; k++) {
        float4 w4 = ((const float4*)&Ws[k][0])[tc];
        float x0 = Xs[tr + 0][k], x1 = Xs[tr + 1][k];
        float x2 = Xs[tr + 2][k], x3 = Xs[tr + 3][k];
        acc[0][0] += x0 * w4.x; acc[0][1] += x0 * w4.y; acc[0][2] += x0 * w4.z; acc[0][3] += x0 * w4.w;
        acc[1][0] += x1 * w4.x; acc[1][1] += x1 * w4.y; acc[1][2] += x1 * w4.z; acc[1][3] += x1 * w4.w;
        acc[2][0] += x2 * w4.x; acc[2][1] += x2 * w4.y; acc[2][2] += x2 * w4.z; acc[2][3] += x2 * w4.w;
        acc[3][0] += x3 * w4.x; acc[3][1] += x3 * w4.y; acc[3][2] += x3 * w4.z; acc[3][3] += x3 * w4.w;
    }
#pragma unroll
    for (int i = 0; i < 4; i++) {
        int r = row0 + tr + i;
        if (r < n) {
            float4 v = make_float4(acc[i][0], acc[i][1], acc[i][2], acc[i][3]);
            *(float4*)&Y[(size_t)r * 64 + tc * 4] = v;
        }
    }
}

// ---------------- scan1: per-1024-chunk inclusive scan + dinv ----------------

__global__ void scan1_kernel(int n) {
    __shared__ int sh[1024];
    int g = blockIdx.y;
    int i = blockIdx.x * 1024 + threadIdx.x;
    int v = (i < n) ? g_deg[g][i] : 0;
    if (i < n) g_dinv[g][i] = rsqrtf((float)v + 1.0f);  // self-loop
    sh[threadIdx.x] = v;
    __syncthreads();
#pragma unroll
    for (int off = 1; off < 1024; off <<= 1) {
        int t = (threadIdx.x >= off) ? sh[threadIdx.x - off] : 0;
        __syncthreads();
        sh[threadIdx.x] += t;
        __syncthreads();
    }
    if (i < n) g_incl[g][i] = sh[threadIdx.x];
    if (threadIdx.x == 1023) g_bsum[g][blockIdx.x] = sh[1023];
}

// ---------------- merged: rowptr finalize + h'=dinv*h fp16 conversion ------------
// blocks [0, nb_n): rowptr; blocks [nb_n, nb_n+nb_sc): scale+convert

__global__ void scan3scale_kernel(int n, int E, int nb_n) {
    int g = blockIdx.y;
    int t = threadIdx.x;

    if ((int)blockIdx.x < nb_n) {
        __shared__ int sh_off;
        int chunk = (blockIdx.x * 256) >> 10;   // 256-node block lies in one 1024-chunk
        if (t < 32) {
            int s = 0;
            for (int k = t; k < chunk; k += 32) s += g_bsum[g][k];
#pragma unroll
            for (int o = 16; o; o >>= 1) s += __shfl_down_sync(0xFFFFFFFFu, s, o);
            if (t == 0) sh_off = s;
        }
        __syncthreads();
        int off = sh_off;
        int i = blockIdx.x * 256 + t;
        if (i < n) g_rowptr[g][i] = g_incl[g][i] - g_deg[g][i] + off;  // exclusive
        if (i == 0) g_rowptr[g][n] = E;
        return;
    }

    // scale: g_A(fp16) = dinv * g_B(fp32), 4 cols per thread
    int gid = (blockIdx.x - nb_n) * 256 + t;
    if (gid >= n * 16) return;
    int i = gid >> 4, c = (gid & 15) * 4;
    float dv = g_dinv[g][i];
    float4 v = *(const float4*)&g_B[g][(size_t)i * 64 + c];
    __half2 p0 = __floats2half2_rn(v.x * dv, v.y * dv);
    __half2 p1 = __floats2half2_rn(v.z * dv, v.w * dv);
    uint2 u = make_uint2(*(unsigned*)&p0, *(unsigned*)&p1);
    *(uint2*)&g_A[g][(size_t)i * 64 + c] = u;
}

// ---------------- claim: atomic-free CSR scatter via precomputed rank ------------

__global__ void claim_kernel(const int* __restrict__ e0, const int* __restrict__ e1,
                             int E, int n) {
    int g = blockIdx.y;
    const int* base = (g == 0 ? e0 : e1);
    int e = blockIdx.x * blockDim.x + threadIdx.x;
    if (e >= E) return;
    int s = clampi(base[e], 0, n - 1);
    int d = clampi(base[E + e], 0, n - 1);
    int pos = g_rowptr[g][d] + g_rank[g][e];
    g_esrc[g][pos] = s;
}

// ---------------- layer-2 GEMM: h' = dinv * (relu(Z1) @ W2), fp16 ----------------

__global__ void gemm64_kernel(const float* __restrict__ W, int n) {
    __shared__ float Ws[64][64];
    __shared__ float Xs[64][65];
    int g = blockIdx.y;
    const float* X = g_B[g];
    __half* Y = g_A[g];
    int tid = threadIdx.x;
    for (int i = tid; i < 64 * 16; i += 256)
        ((float4*)Ws)[i] = ((const float4*)W)[i];
    int row0 = blockIdx.x * 64;
    for (int i = tid; i < 64 * 16; i += 256) {
        int r = i >> 4, c = (i & 15) * 4;
        float4 v = make_float4(0.f, 0.f, 0.f, 0.f);
        if (row0 + r < n) v = *(const float4*)&X[(size_t)(row0 + r) * 64 + c];
        v.x = fmaxf(v.x, 0.f); v.y = fmaxf(v.y, 0.f);
        v.z = fmaxf(v.z, 0.f); v.w = fmaxf(v.w, 0.f);
        Xs[r][c] = v.x; Xs[r][c + 1] = v.y; Xs[r][c + 2] = v.z; Xs[r][c + 3] = v.w;
    }
    __syncthreads();
    int tr = (tid >> 4) * 4;
    int tc = tid & 15;
    float acc[4][4] = {};
#pragma unroll
    for (int k = 0; k < 64; k++) {
        float4 w4 = ((const float4*)&Ws[k][0])[tc];
        float x0 = Xs[tr + 0][k], x1 = Xs[tr + 1][k];
        float x2 = Xs[tr + 2][k], x3 = Xs[tr + 3][k];
        acc[0][0] += x0 * w4.x; acc[0][1] += x0 * w4.y; acc[0][2] += x0 * w4.z; acc[0][3] += x0 * w4.w;
        acc[1][0] += x1 * w4.x; acc[1][1] += x1 * w4.y; acc[1][2] += x1 * w4.z; acc[1][3] += x1 * w4.w;
        acc[2][0] += x2 * w4.x; acc[2][1] += x2 * w4.y; acc[2][2] += x2 * w4.z; acc[2][3] += x2 * w4.w;
        acc[3][0] += x3 * w4.x; acc[3][1] += x3 * w4.y; acc[3][2] += x3 * w4.z; acc[3][3] += x3 * w4.w;
    }
#pragma unroll
    for (int i = 0; i < 4; i++) {
        int r = row0 + tr + i;
        if (r < n) {
            float dv = g_dinv[g][r];
            __half2 p0 = __floats2half2_rn(acc[i][0] * dv, acc[i][1] * dv);
            __half2 p1 = __floats2half2_rn(acc[i][2] * dv, acc[i][3] * dv);
            uint2 u = make_uint2(*(unsigned*)&p0, *(unsigned*)&p1);
            *(uint2*)&Y[(size_t)r * 64 + tc * 4] = u;
        }
    }
}

// ---------------- aggregation: Z = dinv[d]*(Σ h'[src] + h'[d]) + b ----------------
// one warp per node, lane owns 2 cols; fused heads on layer 2

__global__ void agg_kernel(const float* __restrict__ b, int n,
                           const float* __restrict__ Wy, const float* __restrict__ by,
                           const float* __restrict__ Wp, const float* __restrict__ bp,
                           const float* __restrict__ Wb, const float* __restrict__ bb,
                           float* __restrict__ out) {
    int g = blockIdx.y;
    int warp = (blockIdx.x * blockDim.x + threadIdx.x) >> 5;
    int lane = threadIdx.x & 31;
    if (warp >= n) return;
    const __half2* __restrict__ h2 = (const __half2*)g_A[g];
    const int*     __restrict__ ep = g_esrc[g];

    float2 hv = __half22float2(h2[warp * 32 + lane]);  // self (dinv-scaled)
    float ax0 = hv.x, ay0 = hv.y;
    float ax1 = 0.f, ay1 = 0.f;

    int j = g_rowptr[g][warp];
    int end = g_rowptr[g][warp + 1];

    for (; j + 4 <= end; j += 4) {
        int s0 = ep[j], s1 = ep[j + 1], s2 = ep[j + 2], s3 = ep[j + 3];
        float2 v0 = __half22float2(h2[s0 * 32 + lane]);
        float2 v1 = __half22float2(h2[s1 * 32 + lane]);
        float2 v2 = __half22float2(h2[s2 * 32 + lane]);
        float2 v3 = __half22float2(h2[s3 * 32 + lane]);
        ax0 += v0.x; ay0 += v0.y;
        ax1 += v1.x; ay1 += v1.y;
        ax0 += v2.x; ay0 += v2.y;
        ax1 += v3.x; ay1 += v3.y;
    }
    for (; j < end; j++) {
        float2 v0 = __half22float2(h2[ep[j] * 32 + lane]);
        ax0 += v0.x; ay0 += v0.y;
    }
    float dd = g_dinv[g][warp];
    float2 bv = *(const float2*)&b[lane * 2];
    float zx = fmaf(dd, ax0 + ax1, bv.x);
    float zy = fmaf(dd, ay0 + ay1, bv.y);

    if (!Wy) {  // layer 1: store Z1 (fp32)
        *(float2*)&g_B[g][(size_t)warp * 64 + lane * 2] = make_float2(zx, zy);
        return;
    }
    // layer 2: fused heads
    if (g == 0) {
        float2 wy = *(const float2*)&Wy[lane * 2];
        float2 wp = *(const float2*)&Wp[lane * 2];
        float2 wb = *(const float2*)&Wb[lane * 2];
        float sy = zx * wy.x + zy * wy.y;
        float sp = zx * wp.x + zy * wp.y;
        float sb = zx * wb.x + zy * wb.y;
#pragma unroll
        for (int o = 16; o; o >>= 1) {
            sy += __shfl_down_sync(0xFFFFFFFFu, sy, o);
            sp += __shfl_down_sync(0xFFFFFFFFu, sp, o);
            sb += __shfl_down_sync(0xFFFFFFFFu, sb, o);
        }
        if (lane == 0) {
            out[warp]                 = fmaxf(sy + by[0], 0.f);  // yi
            out[(size_t)n + warp]     = fmaxf(sp + bp[0], 0.f);  // fprob
            out[(size_t)3 * n + warp] = fmaxf(sb + bb[0], 0.f);  // treat_prob
        }
    } else {
        float2 wp = *(const float2*)&Wp[lane * 2];
        float sf = zx * wp.x + zy * wp.y;
#pragma unroll
        for (int o = 16; o; o >>= 1)
            sf += __shfl_down_sync(0xFFFFFFFFu, sf, o);
        if (lane == 0)
            out[(size_t)2 * n + warp] = fmaxf(sf + bp[0], 0.f);  // fprob_f
    }
}

// ---------------- launch ----------------

extern "C" void kernel_launch(void* const* d_in, const int* in_sizes, int n_in,
                              void* d_out, int out_size) {
    const float* x   = (const float*)d_in[0];
    const int*   ei  = (const int*)d_in[1];    // int32 on the wire (JAX x64 disabled)
    const float* fx  = (const float*)d_in[2];
    const int*   fei = (const int*)d_in[3];
    const float* W1 = (const float*)d_in[4];
    const float* b1 = (const float*)d_in[5];
    const float* W2 = (const float*)d_in[6];
    const float* b2 = (const float*)d_in[7];
    const float* Wy = (const float*)d_in[8];
    const float* by = (const float*)d_in[9];
    const float* Wp = (const float*)d_in[10];
    const float* bp = (const float*)d_in[11];
    const float* Wb = (const float*)d_in[12];
    const float* bb = (const float*)d_in[13];

    int n = in_sizes[0] / 64;
    int E = in_sizes[1] / 2;
    float* out = (float*)d_out;

    int nb_e  = (E + 255) / 256;
    int nb_g  = (n + 63) / 64;
    int nb_s  = (n + 1023) / 1024;
    int nb_n  = (n + 255) / 256;
    int nb_sc = (n * 16 + 255) / 256;

    dim3 ghg(nb_e + nb_g, 2);
    dim3 gs(nb_s, 2);
    dim3 g3s(nb_n + nb_sc, 2);
    dim3 ge(nb_e, 2);
    dim3 gg(nb_g, 2);
    dim3 gw((n * 32 + 255) / 256, 2);

    // zero degree arrays
    void* deg_ptr;
    cudaGetSymbolAddress(&deg_ptr, g_deg);
    cudaMemsetAsync(deg_ptr, 0, sizeof(int) * 2 * N_CAP);

    // hist (claims per-edge rank) overlapped with layer-1 GEMM (fp32 h -> g_B)
    histgemm_kernel<<<ghg, 256>>>(ei, fei, x, fx, W1, E, n, nb_e);
    scan1_kernel<<<gs, 1024>>>(n);                 // deg scan + dinv
    scan3scale_kernel<<<g3s, 256>>>(n, E, nb_n);   // rowptr + h'=dinv*h fp16
    claim_kernel<<<ge, 256>>>(ei, fei, E, n);      // atomic-free CSR scatter

    // Z1 = dinv*(gather + self) + b1
    agg_kernel<<<gw, 256>>>(b1, n, nullptr, nullptr, nullptr, nullptr, nullptr, nullptr, nullptr);

    // layer 2: h' = dinv * relu(Z1)@W2 ; Z2 + fused heads -> out
    gemm64_kernel<<<gg, 256>>>(W2, n);
    agg_kernel<<<gw, 256>>>(b2, n, Wy, by, Wp, bp, Wb, bb, out);
}

// round 8
// speedup vs baseline: 1.0085x; 1.0085x over previous
#include <cuda_runtime.h>
#include <cuda_fp16.h>
#include <cstdint>

#define N_CAP 100000
#define E_CAP 1600000

// ---------------- scratch (__device__ globals) ----------------
__device__ float  g_dinv[2][N_CAP];
__device__ int    g_deg[2][N_CAP];
__device__ int    g_incl[2][N_CAP];
__device__ int    g_rowptr[2][N_CAP + 1];
__device__ int    g_bsum[2][128];
__device__ int    g_rank[2][E_CAP];             // per-edge rank within its dst row
__device__ int    g_esrc[2][E_CAP];             // dst-sorted src ids
__device__ __half g_A[2][(size_t)N_CAP * 64];   // h' = dinv * (X @ W), fp16
__device__ float  g_B[2][(size_t)N_CAP * 64];   // Z1 (fp32)

static __device__ __forceinline__ int clampi(int v, int lo, int hi) {
    return v < lo ? lo : (v > hi ? hi : v);
}

// ---------------- hist: per-edge rank claim (standalone, high occupancy) ---------
// 2 independent edges per thread for atomic MLP

__global__ void hist_kernel(const int* __restrict__ e0, const int* __restrict__ e1,
                            int E, int n) {
    int g = blockIdx.y;
    const int* dst = (g == 0 ? e0 : e1) + E;
    int e = blockIdx.x * 512 + threadIdx.x;
    if (e < E) {
        int d = clampi(dst[e], 0, n - 1);
        g_rank[g][e] = atomicAdd(&g_deg[g][d], 1);
    }
    int e2 = e + 256;
    if (e2 < E) {
        int d = clampi(dst[e2], 0, n - 1);
        g_rank[g][e2] = atomicAdd(&g_deg[g][d], 1);
    }
}

// ---------------- scan1: per-1024-chunk inclusive scan + dinv ----------------

__global__ void scan1_kernel(int n) {
    __shared__ int sh[1024];
    int g = blockIdx.y;
    int i = blockIdx.x * 1024 + threadIdx.x;
    int v = (i < n) ? g_deg[g][i] : 0;
    if (i < n) g_dinv[g][i] = rsqrtf((float)v + 1.0f);  // self-loop
    sh[threadIdx.x] = v;
    __syncthreads();
#pragma unroll
    for (int off = 1; off < 1024; off <<= 1) {
        int t = (threadIdx.x >= off) ? sh[threadIdx.x - off] : 0;
        __syncthreads();
        sh[threadIdx.x] += t;
        __syncthreads();
    }
    if (i < n) g_incl[g][i] = sh[threadIdx.x];
    if (threadIdx.x == 1023) g_bsum[g][blockIdx.x] = sh[1023];
}

// ---------------- scan3: rowptr finalize ----------------

__global__ void scan3_kernel(int n, int E) {
    __shared__ int sh_off;
    int g = blockIdx.y;
    int t = threadIdx.x;
    int chunk = (blockIdx.x * 256) >> 10;   // 256-node block lies in one 1024-chunk
    if (t < 32) {
        int s = 0;
        for (int k = t; k < chunk; k += 32) s += g_bsum[g][k];
#pragma unroll
        for (int o = 16; o; o >>= 1) s += __shfl_down_sync(0xFFFFFFFFu, s, o);
        if (t == 0) sh_off = s;
    }
    __syncthreads();
    int off = sh_off;
    int i = blockIdx.x * 256 + t;
    if (i < n) g_rowptr[g][i] = g_incl[g][i] - g_deg[g][i] + off;  // exclusive
    if (i == 0) g_rowptr[g][n] = E;
}

// ---------------- merged: atomic-free claim + layer-1 GEMM (fp16 scaled) --------
// blocks [0, nb_e): claim (latency-tolerant, no dep chains);
// blocks [nb_e, nb_e+nb_g): gemm h' = dinv * (X @ W1) -> fp16

__global__ void claimgemm_kernel(const int* __restrict__ e0, const int* __restrict__ e1,
                                 const float* __restrict__ X0, const float* __restrict__ X1,
                                 const float* __restrict__ W, int E, int n, int nb_e) {
    __shared__ float Ws[64][64];
    __shared__ float Xs[64][65];
    int g = blockIdx.y;
    int tid = threadIdx.x;

    if ((int)blockIdx.x < nb_e) {
        const int* base = (g == 0 ? e0 : e1);
        int e = blockIdx.x * 256 + tid;
        if (e < E) {
            int s = clampi(base[e], 0, n - 1);
            int d = clampi(base[E + e], 0, n - 1);
            int pos = g_rowptr[g][d] + g_rank[g][e];
            g_esrc[g][pos] = s;
        }
        return;
    }

    const float* X = (g == 0 ? X0 : X1);
    __half* Y = g_A[g];
    for (int i = tid; i < 64 * 16; i += 256)
        ((float4*)Ws)[i] = ((const float4*)W)[i];
    int row0 = (blockIdx.x - nb_e) * 64;
    for (int i = tid; i < 64 * 16; i += 256) {
        int r = i >> 4, c = (i & 15) * 4;
        float4 v = make_float4(0.f, 0.f, 0.f, 0.f);
        if (row0 + r < n) v = *(const float4*)&X[(size_t)(row0 + r) * 64 + c];
        Xs[r][c] = v.x; Xs[r][c + 1] = v.y; Xs[r][c + 2] = v.z; Xs[r][c + 3] = v.w;
    }
    __syncthreads();
    int tr = (tid >> 4) * 4;
    int tc = tid & 15;
    float acc[4][4] = {};
#pragma unroll
    for (int k = 0; k < 64; k++) {
        float4 w4 = ((const float4*)&Ws[k][0])[tc];
        float x0 = Xs[tr + 0][k], x1 = Xs[tr + 1][k];
        float x2 = Xs[tr + 2][k], x3 = Xs[tr + 3][k];
        acc[0][0] += x0 * w4.x; acc[0][1] += x0 * w4.y; acc[0][2] += x0 * w4.z; acc[0][3] += x0 * w4.w;
        acc[1][0] += x1 * w4.x; acc[1][1] += x1 * w4.y; acc[1][2] += x1 * w4.z; acc[1][3] += x1 * w4.w;
        acc[2][0] += x2 * w4.x; acc[2][1] += x2 * w4.y; acc[2][2] += x2 * w4.z; acc[2][3] += x2 * w4.w;
        acc[3][0] += x3 * w4.x; acc[3][1] += x3 * w4.y; acc[3][2] += x3 * w4.z; acc[3][3] += x3 * w4.w;
    }
#pragma unroll
    for (int i = 0; i < 4; i++) {
        int r = row0 + tr + i;
        if (r < n) {
            float dv = g_dinv[g][r];
            __half2 p0 = __floats2half2_rn(acc[i][0] * dv, acc[i][1] * dv);
            __half2 p1 = __floats2half2_rn(acc[i][2] * dv, acc[i][3] * dv);
            uint2 u = make_uint2(*(unsigned*)&p0, *(unsigned*)&p1);
            *(uint2*)&Y[(size_t)r * 64 + tc * 4] = u;
        }
    }
}

// ---------------- layer-2 GEMM: h' = dinv * (relu(Z1) @ W2), fp16 ----------------

__global__ void gemm64_kernel(const float* __restrict__ W, int n) {
    __shared__ float Ws[64][64];
    __shared__ float Xs[64][65];
    int g = blockIdx.y;
    const float* X = g_B[g];
    __half* Y = g_A[g];
    int tid = threadIdx.x;
    for (int i = tid; i < 64 * 16; i += 256)
        ((float4*)Ws)[i] = ((const float4*)W)[i];
    int row0 = blockIdx.x * 64;
    for (int i = tid; i < 64 * 16; i += 256) {
        int r = i >> 4, c = (i & 15) * 4;
        float4 v = make_float4(0.f, 0.f, 0.f, 0.f);
        if (row0 + r < n) v = *(const float4*)&X[(size_t)(row0 + r) * 64 + c];
        v.x = fmaxf(v.x, 0.f); v.y = fmaxf(v.y, 0.f);
        v.z = fmaxf(v.z, 0.f); v.w = fmaxf(v.w, 0.f);
        Xs[r][c] = v.x; Xs[r][c + 1] = v.y; Xs[r][c + 2] = v.z; Xs[r][c + 3] = v.w;
    }
    __syncthreads();
    int tr = (tid >> 4) * 4;
    int tc = tid & 15;
    float acc[4][4] = {};
#pragma unroll
    for (int k = 0; k < 64; k++) {
        float4 w4 = ((const float4*)&Ws[k][0])[tc];
        float x0 = Xs[tr + 0][k], x1 = Xs[tr + 1][k];
        float x2 = Xs[tr + 2][k], x3 = Xs[tr + 3][k];
        acc[0][0] += x0 * w4.x; acc[0][1] += x0 * w4.y; acc[0][2] += x0 * w4.z; acc[0][3] += x0 * w4.w;
        acc[1][0] += x1 * w4.x; acc[1][1] += x1 * w4.y; acc[1][2] += x1 * w4.z; acc[1][3] += x1 * w4.w;
        acc[2][0] += x2 * w4.x; acc[2][1] += x2 * w4.y; acc[2][2] += x2 * w4.z; acc[2][3] += x2 * w4.w;
        acc[3][0] += x3 * w4.x; acc[3][1] += x3 * w4.y; acc[3][2] += x3 * w4.z; acc[3][3] += x3 * w4.w;
    }
#pragma unroll
    for (int i = 0; i < 4; i++) {
        int r = row0 + tr + i;
        if (r < n) {
            float dv = g_dinv[g][r];
            __half2 p0 = __floats2half2_rn(acc[i][0] * dv, acc[i][1] * dv);
            __half2 p1 = __floats2half2_rn(acc[i][2] * dv, acc[i][3] * dv);
            uint2 u = make_uint2(*(unsigned*)&p0, *(unsigned*)&p1);
            *(uint2*)&Y[(size_t)r * 64 + tc * 4] = u;
        }
    }
}

// ---------------- aggregation: Z = dinv[d]*(Σ h'[src] + h'[d]) + b ----------------
// one warp per node, lane owns 2 cols; fused heads on layer 2

__global__ void agg_kernel(const float* __restrict__ b, int n,
                           const float* __restrict__ Wy, const float* __restrict__ by,
                           const float* __restrict__ Wp, const float* __restrict__ bp,
                           const float* __restrict__ Wb, const float* __restrict__ bb,
                           float* __restrict__ out) {
    int g = blockIdx.y;
    int warp = (blockIdx.x * blockDim.x + threadIdx.x) >> 5;
    int lane = threadIdx.x & 31;
    if (warp >= n) return;
    const __half2* __restrict__ h2 = (const __half2*)g_A[g];
    const int*     __restrict__ ep = g_esrc[g];

    float2 hv = __half22float2(h2[warp * 32 + lane]);  // self (dinv-scaled)
    float ax0 = hv.x, ay0 = hv.y;
    float ax1 = 0.f, ay1 = 0.f;

    int j = g_rowptr[g][warp];
    int end = g_rowptr[g][warp + 1];

    for (; j + 4 <= end; j += 4) {
        int s0 = ep[j], s1 = ep[j + 1], s2 = ep[j + 2], s3 = ep[j + 3];
        float2 v0 = __half22float2(h2[s0 * 32 + lane]);
        float2 v1 = __half22float2(h2[s1 * 32 + lane]);
        float2 v2 = __half22float2(h2[s2 * 32 + lane]);
        float2 v3 = __half22float2(h2[s3 * 32 + lane]);
        ax0 += v0.x; ay0 += v0.y;
        ax1 += v1.x; ay1 += v1.y;
        ax0 += v2.x; ay0 += v2.y;
        ax1 += v3.x; ay1 += v3.y;
    }
    for (; j < end; j++) {
        float2 v0 = __half22float2(h2[ep[j] * 32 + lane]);
        ax0 += v0.x; ay0 += v0.y;
    }
    float dd = g_dinv[g][warp];
    float2 bv = *(const float2*)&b[lane * 2];
    float zx = fmaf(dd, ax0 + ax1, bv.x);
    float zy = fmaf(dd, ay0 + ay1, bv.y);

    if (!Wy) {  // layer 1: store Z1 (fp32)
        *(float2*)&g_B[g][(size_t)warp * 64 + lane * 2] = make_float2(zx, zy);
        return;
    }
    // layer 2: fused heads
    if (g == 0) {
        float2 wy = *(const float2*)&Wy[lane * 2];
        float2 wp = *(const float2*)&Wp[lane * 2];
        float2 wb = *(const float2*)&Wb[lane * 2];
        float sy = zx * wy.x + zy * wy.y;
        float sp = zx * wp.x + zy * wp.y;
        float sb = zx * wb.x + zy * wb.y;
#pragma unroll
        for (int o = 16; o; o >>= 1) {
            sy += __shfl_down_sync(0xFFFFFFFFu, sy, o);
            sp += __shfl_down_sync(0xFFFFFFFFu, sp, o);
            sb += __shfl_down_sync(0xFFFFFFFFu, sb, o);
        }
        if (lane == 0) {
            out[warp]                 = fmaxf(sy + by[0], 0.f);  // yi
            out[(size_t)n + warp]     = fmaxf(sp + bp[0], 0.f);  // fprob
            out[(size_t)3 * n + warp] = fmaxf(sb + bb[0], 0.f);  // treat_prob
        }
    } else {
        float2 wp = *(const float2*)&Wp[lane * 2];
        float sf = zx * wp.x + zy * wp.y;
#pragma unroll
        for (int o = 16; o; o >>= 1)
            sf += __shfl_down_sync(0xFFFFFFFFu, sf, o);
        if (lane == 0)
            out[(size_t)2 * n + warp] = fmaxf(sf + bp[0], 0.f);  // fprob_f
    }
}

// ---------------- launch ----------------

extern "C" void kernel_launch(void* const* d_in, const int* in_sizes, int n_in,
                              void* d_out, int out_size) {
    const float* x   = (const float*)d_in[0];
    const int*   ei  = (const int*)d_in[1];    // int32 on the wire (JAX x64 disabled)
    const float* fx  = (const float*)d_in[2];
    const int*   fei = (const int*)d_in[3];
    const float* W1 = (const float*)d_in[4];
    const float* b1 = (const float*)d_in[5];
    const float* W2 = (const float*)d_in[6];
    const float* b2 = (const float*)d_in[7];
    const float* Wy = (const float*)d_in[8];
    const float* by = (const float*)d_in[9];
    const float* Wp = (const float*)d_in[10];
    const float* bp = (const float*)d_in[11];
    const float* Wb = (const float*)d_in[12];
    const float* bb = (const float*)d_in[13];

    int n = in_sizes[0] / 64;
    int E = in_sizes[1] / 2;
    float* out = (float*)d_out;

    int nb_e  = (E + 255) / 256;
    int nb_h  = (E + 511) / 512;
    int nb_g  = (n + 63) / 64;
    int nb_s  = (n + 1023) / 1024;
    int nb_n  = (n + 255) / 256;

    dim3 gh(nb_h, 2);
    dim3 gs(nb_s, 2);
    dim3 g3(nb_n, 2);
    dim3 gcg(nb_e + nb_g, 2);
    dim3 gg(nb_g, 2);
    dim3 gw((n * 32 + 255) / 256, 2);

    // zero degree arrays
    void* deg_ptr;
    cudaGetSymbolAddress(&deg_ptr, g_deg);
    cudaMemsetAsync(deg_ptr, 0, sizeof(int) * 2 * N_CAP);

    // CSR build
    hist_kernel<<<gh, 256>>>(ei, fei, E, n);       // rank claim, high occupancy
    scan1_kernel<<<gs, 1024>>>(n);                 // deg scan + dinv
    scan3_kernel<<<g3, 256>>>(n, E);               // rowptr

    // atomic-free claim overlapped with layer-1 GEMM (h' = dinv * X@W1, fp16)
    claimgemm_kernel<<<gcg, 256>>>(ei, fei, x, fx, W1, E, n, nb_e);

    // Z1 = dinv*(gather + self) + b1
    agg_kernel<<<gw, 256>>>(b1, n, nullptr, nullptr, nullptr, nullptr, nullptr, nullptr, nullptr);

    // layer 2: h' = dinv * relu(Z1)@W2 ; Z2 + fused heads -> out
    gemm64_kernel<<<gg, 256>>>(W2, n);
    agg_kernel<<<gw, 256>>>(b2, n, Wy, by, Wp, bp, Wb, bb, out);
}

// round 9
// speedup vs baseline: 1.0140x; 1.0054x over previous
#include <cuda_runtime.h>
#include <cuda_fp16.h>
#include <cstdint>

#define N_CAP 100000
#define E_CAP 1600000

// ---------------- scratch (__device__ globals, zero-initialized) ----------------
__device__ float  g_dinv[2][N_CAP];
__device__ int    g_deg[2][N_CAP];        // must be zero at entry; scan3 re-zeroes
__device__ int    g_incl[2][N_CAP];
__device__ int    g_rowptr[2][N_CAP + 1];
__device__ int    g_bsum[2][128];
__device__ int    g_rank[2][E_CAP];       // per-edge rank within its dst row
__device__ int    g_esrc[2][E_CAP];       // dst-sorted src ids
__device__ __half g_A[2][(size_t)N_CAP * 64];   // h' = dinv * (X @ W), fp16
__device__ float  g_B[2][(size_t)N_CAP * 64];   // Z1 (fp32)

static __device__ __forceinline__ int clampi(int v, int lo, int hi) {
    return v < lo ? lo : (v > hi ? hi : v);
}

// ---------------- hist: per-edge rank claim (4 edges/thread, atomic MLP) ---------

__global__ void hist_kernel(const int* __restrict__ e0, const int* __restrict__ e1,
                            int E, int n) {
    int g = blockIdx.y;
    const int* dst = (g == 0 ? e0 : e1) + E;
    int base_e = blockIdx.x * 1024 + threadIdx.x;
#pragma unroll
    for (int k = 0; k < 4; k++) {
        int e = base_e + k * 256;
        if (e < E) {
            int d = clampi(dst[e], 0, n - 1);
            g_rank[g][e] = atomicAdd(&g_deg[g][d], 1);
        }
    }
}

// ---------------- scan1: per-1024-chunk inclusive scan + dinv ----------------

__global__ void scan1_kernel(int n) {
    __shared__ int sh[1024];
    int g = blockIdx.y;
    int i = blockIdx.x * 1024 + threadIdx.x;
    int v = (i < n) ? g_deg[g][i] : 0;
    if (i < n) g_dinv[g][i] = rsqrtf((float)v + 1.0f);  // self-loop
    sh[threadIdx.x] = v;
    __syncthreads();
#pragma unroll
    for (int off = 1; off < 1024; off <<= 1) {
        int t = (threadIdx.x >= off) ? sh[threadIdx.x - off] : 0;
        __syncthreads();
        sh[threadIdx.x] += t;
        __syncthreads();
    }
    if (i < n) g_incl[g][i] = sh[threadIdx.x];
    if (threadIdx.x == 1023) g_bsum[g][blockIdx.x] = sh[1023];
}

// ---------------- scan3: rowptr finalize + deg reset (for next graph replay) -----

__global__ void scan3_kernel(int n, int E) {
    __shared__ int sh_off;
    int g = blockIdx.y;
    int t = threadIdx.x;
    int chunk = (blockIdx.x * 256) >> 10;
    if (t < 32) {
        int s = 0;
        for (int k = t; k < chunk; k += 32) s += g_bsum[g][k];
#pragma unroll
        for (int o = 16; o; o >>= 1) s += __shfl_down_sync(0xFFFFFFFFu, s, o);
        if (t == 0) sh_off = s;
    }
    __syncthreads();
    int off = sh_off;
    int i = blockIdx.x * 256 + t;
    if (i < n) {
        g_rowptr[g][i] = g_incl[g][i] - g_deg[g][i] + off;  // exclusive
        g_deg[g][i] = 0;                                     // reset invariant
    }
    if (i == 0) g_rowptr[g][n] = E;
}

// ---------------- claim: atomic-free CSR scatter (4 edges/thread MLP) ------------

__global__ void claim_kernel(const int* __restrict__ e0, const int* __restrict__ e1,
                             int E, int n) {
    int g = blockIdx.y;
    const int* base = (g == 0 ? e0 : e1);
    int base_e = blockIdx.x * 1024 + threadIdx.x;
#pragma unroll
    for (int k = 0; k < 4; k++) {
        int e = base_e + k * 256;
        if (e < E) {
            int s = clampi(base[e], 0, n - 1);
            int d = clampi(base[E + e], 0, n - 1);
            int pos = g_rowptr[g][d] + g_rank[g][e];
            g_esrc[g][pos] = s;
        }
    }
}

// ---------------- GEMM: h' = dinv * ((relu?)X @ W), fp16 out ----------------

__global__ void gemm64_kernel(const float* __restrict__ X0, const float* __restrict__ X1,
                              int use_B, const float* __restrict__ W, int n, int relu_in) {
    __shared__ float Ws[64][64];
    __shared__ float Xs[64][65];
    int g = blockIdx.y;
    const float* X = use_B ? (const float*)g_B[g] : (g == 0 ? X0 : X1);
    __half* Y = g_A[g];
    int tid = threadIdx.x;
    for (int i = tid; i < 64 * 16; i += 256)
        ((float4*)Ws)[i] = ((const float4*)W)[i];
    int row0 = blockIdx.x * 64;
    for (int i = tid; i < 64 * 16; i += 256) {
        int r = i >> 4, c = (i & 15) * 4;
        float4 v = make_float4(0.f, 0.f, 0.f, 0.f);
        if (row0 + r < n) v = *(const float4*)&X[(size_t)(row0 + r) * 64 + c];
        if (relu_in) {
            v.x = fmaxf(v.x, 0.f); v.y = fmaxf(v.y, 0.f);
            v.z = fmaxf(v.z, 0.f); v.w = fmaxf(v.w, 0.f);
        }
        Xs[r][c] = v.x; Xs[r][c + 1] = v.y; Xs[r][c + 2] = v.z; Xs[r][c + 3] = v.w;
    }
    __syncthreads();
    int tr = (tid >> 4) * 4;
    int tc = tid & 15;
    float acc[4][4] = {};
#pragma unroll
    for (int k = 0; k < 64; k++) {
        float4 w4 = ((const float4*)&Ws[k][0])[tc];
        float x0 = Xs[tr + 0][k], x1 = Xs[tr + 1][k];
        float x2 = Xs[tr + 2][k], x3 = Xs[tr + 3][k];
        acc[0][0] += x0 * w4.x; acc[0][1] += x0 * w4.y; acc[0][2] += x0 * w4.z; acc[0][3] += x0 * w4.w;
        acc[1][0] += x1 * w4.x; acc[1][1] += x1 * w4.y; acc[1][2] += x1 * w4.z; acc[1][3] += x1 * w4.w;
        acc[2][0] += x2 * w4.x; acc[2][1] += x2 * w4.y; acc[2][2] += x2 * w4.z; acc[2][3] += x2 * w4.w;
        acc[3][0] += x3 * w4.x; acc[3][1] += x3 * w4.y; acc[3][2] += x3 * w4.z; acc[3][3] += x3 * w4.w;
    }
#pragma unroll
    for (int i = 0; i < 4; i++) {
        int r = row0 + tr + i;
        if (r < n) {
            float dv = g_dinv[g][r];
            __half2 p0 = __floats2half2_rn(acc[i][0] * dv, acc[i][1] * dv);
            __half2 p1 = __floats2half2_rn(acc[i][2] * dv, acc[i][3] * dv);
            uint2 u = make_uint2(*(unsigned*)&p0, *(unsigned*)&p1);
            *(uint2*)&Y[(size_t)r * 64 + tc * 4] = u;
        }
    }
}

// ---------------- aggregation: Z = dinv[d]*(Σ h'[src] + h'[d]) + b ----------------
// warp per node; lanes split 16/16 so each load instruction covers TWO edge rows.
// 4 slots -> 8 edges in flight per warp. shfl_xor(16) folds the halves.

__global__ void agg_kernel(const float* __restrict__ b, int n,
                           const float* __restrict__ Wy, const float* __restrict__ by,
                           const float* __restrict__ Wp, const float* __restrict__ bp,
                           const float* __restrict__ Wb, const float* __restrict__ bb,
                           float* __restrict__ out) {
    int g = blockIdx.y;
    int node = (blockIdx.x * blockDim.x + threadIdx.x) >> 5;
    int lane = threadIdx.x & 31;
    if (node >= n) return;
    const uint2* __restrict__ h4 = (const uint2*)g_A[g];  // 16 uint2 per row (4 cols each)
    const int*   __restrict__ ep = g_esrc[g];

    int half = lane >> 4;   // 0/1: which edge of the pair
    int c4   = lane & 15;   // col group: cols 4*c4 .. 4*c4+3
    float a0 = 0.f, a1 = 0.f, a2 = 0.f, a3 = 0.f;

    int beg = g_rowptr[g][node];
    int end = g_rowptr[g][node + 1];

    for (int jj = beg; jj < end; jj += 8) {
#pragma unroll
        for (int s = 0; s < 4; s++) {
            int my = jj + s * 2 + half;
            if (my < end) {
                int src = ep[my];
                uint2 u = h4[(size_t)src * 16 + c4];
                float2 f0 = __half22float2(*(__half2*)&u.x);
                float2 f1 = __half22float2(*(__half2*)&u.y);
                a0 += f0.x; a1 += f0.y; a2 += f1.x; a3 += f1.y;
            }
        }
    }
    // fold edge-halves
    a0 += __shfl_xor_sync(0xFFFFFFFFu, a0, 16);
    a1 += __shfl_xor_sync(0xFFFFFFFFu, a1, 16);
    a2 += __shfl_xor_sync(0xFFFFFFFFu, a2, 16);
    a3 += __shfl_xor_sync(0xFFFFFFFFu, a3, 16);

    // self + scale + bias (all lanes compute; lanes 0-15 hold the canonical copy)
    uint2 us = h4[(size_t)node * 16 + c4];
    float2 s0 = __half22float2(*(__half2*)&us.x);
    float2 s1 = __half22float2(*(__half2*)&us.y);
    float dd = g_dinv[g][node];
    const float4 bv = *(const float4*)&b[c4 * 4];
    float z0 = fmaf(dd, a0 + s0.x, bv.x);
    float z1 = fmaf(dd, a1 + s0.y, bv.y);
    float z2 = fmaf(dd, a2 + s1.x, bv.z);
    float z3 = fmaf(dd, a3 + s1.y, bv.w);

    if (!Wy) {  // layer 1: store Z1 (fp32), lanes 0-15 cover all 64 cols
        if (half == 0)
            *(float4*)&g_B[g][(size_t)node * 64 + c4 * 4] = make_float4(z0, z1, z2, z3);
        return;
    }
    // layer 2: fused heads — partial dots per lane, reduce within 16-lane segment
    if (g == 0) {
        float4 wy = *(const float4*)&Wy[c4 * 4];
        float4 wp = *(const float4*)&Wp[c4 * 4];
        float4 wb = *(const float4*)&Wb[c4 * 4];
        float sy = z0 * wy.x + z1 * wy.y + z2 * wy.z + z3 * wy.w;
        float sp = z0 * wp.x + z1 * wp.y + z2 * wp.z + z3 * wp.w;
        float sb = z0 * wb.x + z1 * wb.y + z2 * wb.z + z3 * wb.w;
#pragma unroll
        for (int o = 8; o; o >>= 1) {
            sy += __shfl_down_sync(0xFFFFFFFFu, sy, o, 16);
            sp += __shfl_down_sync(0xFFFFFFFFu, sp, o, 16);
            sb += __shfl_down_sync(0xFFFFFFFFu, sb, o, 16);
        }
        if (lane == 0) {
            out[node]                 = fmaxf(sy + by[0], 0.f);  // yi
            out[(size_t)n + node]     = fmaxf(sp + bp[0], 0.f);  // fprob
            out[(size_t)3 * n + node] = fmaxf(sb + bb[0], 0.f);  // treat_prob
        }
    } else {
        float4 wp = *(const float4*)&Wp[c4 * 4];
        float sf = z0 * wp.x + z1 * wp.y + z2 * wp.z + z3 * wp.w;
#pragma unroll
        for (int o = 8; o; o >>= 1)
            sf += __shfl_down_sync(0xFFFFFFFFu, sf, o, 16);
        if (lane == 0)
            out[(size_t)2 * n + node] = fmaxf(sf + bp[0], 0.f);  // fprob_f
    }
}

// ---------------- launch ----------------

extern "C" void kernel_launch(void* const* d_in, const int* in_sizes, int n_in,
                              void* d_out, int out_size) {
    const float* x   = (const float*)d_in[0];
    const int*   ei  = (const int*)d_in[1];    // int32 on the wire (JAX x64 disabled)
    const float* fx  = (const float*)d_in[2];
    const int*   fei = (const int*)d_in[3];
    const float* W1 = (const float*)d_in[4];
    const float* b1 = (const float*)d_in[5];
    const float* W2 = (const float*)d_in[6];
    const float* b2 = (const float*)d_in[7];
    const float* Wy = (const float*)d_in[8];
    const float* by = (const float*)d_in[9];
    const float* Wp = (const float*)d_in[10];
    const float* bp = (const float*)d_in[11];
    const float* Wb = (const float*)d_in[12];
    const float* bb = (const float*)d_in[13];

    int n = in_sizes[0] / 64;
    int E = in_sizes[1] / 2;
    float* out = (float*)d_out;

    dim3 ge4((E + 1023) / 1024, 2);
    dim3 gs((n + 1023) / 1024, 2);
    dim3 g3((n + 255) / 256, 2);
    dim3 gg((n + 63) / 64, 2);
    dim3 gw((n * 32 + 255) / 256, 2);

    // CSR build (deg starts zero: module init / scan3 reset)
    hist_kernel<<<ge4, 256>>>(ei, fei, E, n);      // rank claim
    scan1_kernel<<<gs, 1024>>>(n);                 // deg scan + dinv
    scan3_kernel<<<g3, 256>>>(n, E);               // rowptr + deg reset
    claim_kernel<<<ge4, 256>>>(ei, fei, E, n);     // atomic-free CSR scatter

    // layer 1
    gemm64_kernel<<<gg, 256>>>(x, fx, 0, W1, n, 0);
    agg_kernel<<<gw, 256>>>(b1, n, nullptr, nullptr, nullptr, nullptr, nullptr, nullptr, nullptr);

    // layer 2 (+ fused heads)
    gemm64_kernel<<<gg, 256>>>(nullptr, nullptr, 1, W2, n, 1);
    agg_kernel<<<gw, 256>>>(b2, n, Wy, by, Wp, bp, Wb, bb, out);
}